// round 13
// baseline (speedup 1.0000x reference)
#include <cuda_runtime.h>
#include <cuda_fp16.h>
#include <math.h>
#include <stdint.h>

#define B_ 4
#define L_ 4096
#define D_ 1024
#define M_ (B_*L_)            // 16384 rows
#define TOT (M_*D_)           // 16777216 elements per tensor
#define NCHUNK 128
#define CLEN (L_/NCHUNK)      // 32
#define KT (D_/16)            // 64 k-tiles of 16

// ---- GEMM tiling: block 128(M) x 256(N), 8 warps 2x4, warp tile 64x64, fp16 ----
// EXACT R10 configuration (759us run) — proven local optimum, do not perturb.
#define STAGES 5
#define AST 24                 // halves per A row (16 + 8 pad) -> 48B, conflict-free
#define BST 24
#define A_STAGE (128*AST)      // 3072 halves
#define B_STAGE (256*BST)      // 6144 halves
#define STAGE_HALVES (A_STAGE + B_STAGE)        // 9216 (18KB)
#define SMEM_BYTES (STAGES*STAGE_HALVES*2)      // 92160

// ---- scratch (device globals: no runtime allocation allowed) ----
__device__ float  g_alpha[TOT];
__device__ float  g_x    [TOT];     // v * silu(beta_logits)
__device__ float  g_h    [TOT];
__device__ __half g_norm16[TOT];
__device__ __half g_h16  [TOT];
__device__ float  g_Aprod[B_*NCHUNK*D_];
__device__ float  g_hend [B_*NCHUNK*D_];
__device__ float  g_carry[B_*NCHUNK*D_];
__device__ __half g_WaT16[D_*D_];
__device__ __half g_WbT16[D_*D_];
__device__ __half g_WcT16[D_*D_];

__device__ __forceinline__ float sigmoidf_(float z) { return 1.f / (1.f + expf(-z)); }
__device__ __forceinline__ float siluf_(float z)    { return z   / (1.f + expf(-z)); }

__device__ __forceinline__ void mma_f16(float c[4],
    uint32_t a0, uint32_t a1, uint32_t a2, uint32_t a3, uint32_t b0, uint32_t b1) {
    asm volatile(
        "mma.sync.aligned.m16n8k16.row.col.f32.f16.f16.f32 "
        "{%0,%1,%2,%3},{%4,%5,%6,%7},{%8,%9},{%0,%1,%2,%3};"
        : "+f"(c[0]), "+f"(c[1]), "+f"(c[2]), "+f"(c[3])
        : "r"(a0), "r"(a1), "r"(a2), "r"(a3), "r"(b0), "r"(b1));
}
__device__ __forceinline__ void cp16(void* dst, const void* src) {
    uint32_t d = (uint32_t)__cvta_generic_to_shared(dst);
    asm volatile("cp.async.cg.shared.global [%0], [%1], 16;" :: "r"(d), "l"(src));
}
#define CP_COMMIT()  asm volatile("cp.async.commit_group;")
#define CP_WAIT3()   asm volatile("cp.async.wait_group 3;")

// ---------------------------------------------------------------------------
// RMS norm -> half output
// ---------------------------------------------------------------------------
__global__ void rms_kernel(const float* __restrict__ ctx, const float* __restrict__ g) {
    int row = blockIdx.x;
    const float* x = ctx + (size_t)row * D_;
    float s = 0.f;
    #pragma unroll
    for (int i = threadIdx.x; i < D_; i += 256) { float v = x[i]; s += v * v; }
    __shared__ float red[8];
    #pragma unroll
    for (int o = 16; o > 0; o >>= 1) s += __shfl_xor_sync(0xffffffffu, s, o);
    if ((threadIdx.x & 31) == 0) red[threadIdx.x >> 5] = s;
    __syncthreads();
    if (threadIdx.x < 8) {
        float t = red[threadIdx.x];
        #pragma unroll
        for (int o = 4; o > 0; o >>= 1) t += __shfl_xor_sync(0xffu, t, o);
        if (threadIdx.x == 0) red[0] = t;
    }
    __syncthreads();
    float inv = rsqrtf(red[0] * (1.f / D_) + 1e-6f);
    __half* y = g_norm16 + (size_t)row * D_;
    for (int i = threadIdx.x; i < D_; i += 256) y[i] = __float2half(x[i] * inv * g[i]);
}

// ---------------------------------------------------------------------------
// Transpose + fp32->fp16 convert of weights: WT16[n*D+k] = half(W[k*D+n])
// ---------------------------------------------------------------------------
__global__ void transpose3_kernel(const float* __restrict__ Wa,
                                  const float* __restrict__ Wb,
                                  const float* __restrict__ Wc) {
    __shared__ float t[32][33];
    const float* src = (blockIdx.z == 0) ? Wa : (blockIdx.z == 1) ? Wb : Wc;
    __half* dst = (blockIdx.z == 0) ? g_WaT16 : (blockIdx.z == 1) ? g_WbT16 : g_WcT16;
    int x = blockIdx.x * 32 + threadIdx.x;
    int y0 = blockIdx.y * 32;
    #pragma unroll
    for (int j = 0; j < 32; j += 8)
        t[threadIdx.y + j][threadIdx.x] = src[(size_t)(y0 + threadIdx.y + j) * D_ + x];
    __syncthreads();
    int x2 = blockIdx.y * 32 + threadIdx.x;
    int y2 = blockIdx.x * 32;
    #pragma unroll
    for (int j = 0; j < 32; j += 8)
        dst[(size_t)(y2 + threadIdx.y + j) * D_ + x2] = __float2half(t[threadIdx.x][threadIdx.y + j]);
}

// ---------------------------------------------------------------------------
// fp16 mainloop — EXACT R7/R10 structure (5 stages, WAIT3, two barriers,
// loads after compute, 256 threads). Measured-good; do not perturb.
// ---------------------------------------------------------------------------
__device__ __forceinline__ void gemm_core(
    __half* sm, const __half* __restrict__ A16, const __half* __restrict__ WT,
    int m0, int ncol0, float acc[4][8][4])
{
    const int tid = threadIdx.x;

    auto ld_stage = [&](int stage, int kt) {
        const int k0 = kt * 16;
        __half* As = sm + stage * STAGE_HALVES;
        __half* Bs = As + A_STAGE;
        {   // A: 128 rows x 2 chunks of 8 halves
            int r = tid >> 1, q = tid & 1;
            cp16(As + r * AST + q * 8, A16 + (size_t)(m0 + r) * D_ + k0 + q * 8);
        }
        #pragma unroll
        for (int i = 0; i < 2; i++) {   // B: 256 rows x 2 chunks
            int idx = tid + i * 256;
            int r = idx >> 1, q = idx & 1;
            cp16(Bs + r * BST + q * 8, WT + (size_t)(ncol0 + r) * D_ + k0 + q * 8);
        }
    };

    const int lane = tid & 31;
    const int gid = lane >> 2, tig = lane & 3;
    const int wid = tid >> 5;
    const int wm = (wid >> 2) * 64;       // 0 / 64
    const int wn = (wid & 3) * 64;        // 0..192

    #pragma unroll
    for (int s = 0; s < STAGES - 1; s++) { ld_stage(s, s); CP_COMMIT(); }

    int s_cur = 0, s_ld = STAGES - 1;
    for (int kt = 0; kt < KT; kt++) {
        CP_WAIT3();
        __syncthreads();

        const __half* as = sm + s_cur * STAGE_HALVES;
        const __half* bs = as + A_STAGE;

        uint32_t af[4][4], bf[8][2];
        #pragma unroll
        for (int mt = 0; mt < 4; mt++) {
            int r = wm + mt * 16 + gid;
            af[mt][0] = *(const uint32_t*)(as + r * AST + 2 * tig);
            af[mt][1] = *(const uint32_t*)(as + (r + 8) * AST + 2 * tig);
            af[mt][2] = *(const uint32_t*)(as + r * AST + 2 * tig + 8);
            af[mt][3] = *(const uint32_t*)(as + (r + 8) * AST + 2 * tig + 8);
        }
        #pragma unroll
        for (int nt = 0; nt < 8; nt++) {
            int col = wn + nt * 8 + gid;
            bf[nt][0] = *(const uint32_t*)(bs + col * BST + 2 * tig);
            bf[nt][1] = *(const uint32_t*)(bs + col * BST + 2 * tig + 8);
        }
        #pragma unroll
        for (int mt = 0; mt < 4; mt++)
            #pragma unroll
            for (int nt = 0; nt < 8; nt++)
                mma_f16(acc[mt][nt], af[mt][0], af[mt][1], af[mt][2], af[mt][3],
                        bf[nt][0], bf[nt][1]);

        __syncthreads();     // all warps done with s_ld's buffer before overwrite

        int nk = kt + STAGES - 1;
        if (nk < KT) ld_stage(s_ld, nk);
        CP_COMMIT();
        if (++s_cur == STAGES) s_cur = 0;
        if (++s_ld == STAGES) s_ld = 0;
    }
}

// ---------------------------------------------------------------------------
// GEMM 1+2: alpha = sigmoid(.@Wa+ba) -> g_alpha;
//           beta path: g_x = v*silu(.@Wb+bb), o_v = v. grid (8,128)
// ---------------------------------------------------------------------------
__global__ __launch_bounds__(256, 1) void gemm_ab_kernel(
    const float* __restrict__ ba, const float* __restrict__ bb,
    const float* __restrict__ v, float* __restrict__ o_v)
{
    extern __shared__ __half sm[];
    const int m0 = blockIdx.y * 128;
    const bool isA = (blockIdx.x < 4);
    const int ncol0 = (isA ? blockIdx.x : blockIdx.x - 4) * 256;
    const __half* WT  = isA ? g_WaT16 : g_WbT16;
    const float* bias = isA ? ba : bb;

    float acc[4][8][4];
    #pragma unroll
    for (int i = 0; i < 4; i++)
        #pragma unroll
        for (int j = 0; j < 8; j++)
            #pragma unroll
            for (int k = 0; k < 4; k++) acc[i][j][k] = 0.f;

    gemm_core(sm, g_norm16, WT, m0, ncol0, acc);

    const int lane = threadIdx.x & 31;
    const int gid = lane >> 2, tig = lane & 3;
    const int wid = threadIdx.x >> 5;
    const int wm = (wid >> 2) * 64, wn = (wid & 3) * 64;
    #pragma unroll
    for (int mt = 0; mt < 4; mt++) {
        #pragma unroll
        for (int nt = 0; nt < 8; nt++) {
            int col = ncol0 + wn + nt * 8 + 2 * tig;
            #pragma unroll
            for (int half = 0; half < 2; half++) {
                int row = m0 + wm + mt * 16 + gid + half * 8;
                size_t idx = (size_t)row * D_ + col;
                float z0 = acc[mt][nt][half*2+0] + bias[col];
                float z1 = acc[mt][nt][half*2+1] + bias[col+1];
                if (isA) {
                    float2 o; o.x = sigmoidf_(z0); o.y = sigmoidf_(z1);
                    *(float2*)(g_alpha + idx) = o;
                } else {
                    float2 vv = *(const float2*)(v + idx);
                    float2 o; o.x = vv.x * siluf_(z0); o.y = vv.y * siluf_(z1);
                    *(float2*)(g_x + idx) = o;
                    *(float2*)(o_v + idx) = vv;
                }
            }
        }
    }
}

// ---------------------------------------------------------------------------
// GEMM 3: ctx_out = ctx + silu(h @ Wc + bc). grid (4, 128)
// ---------------------------------------------------------------------------
__global__ __launch_bounds__(256, 1) void gemm_ctx_kernel(
    const float* __restrict__ bc,
    const float* __restrict__ ctx, float* __restrict__ out_ctx)
{
    extern __shared__ __half sm[];
    const int m0 = blockIdx.y * 128;
    const int ncol0 = blockIdx.x * 256;

    float acc[4][8][4];
    #pragma unroll
    for (int i = 0; i < 4; i++)
        #pragma unroll
        for (int j = 0; j < 8; j++)
            #pragma unroll
            for (int k = 0; k < 4; k++) acc[i][j][k] = 0.f;

    gemm_core(sm, g_h16, g_WcT16, m0, ncol0, acc);

    const int lane = threadIdx.x & 31;
    const int gid = lane >> 2, tig = lane & 3;
    const int wid = threadIdx.x >> 5;
    const int wm = (wid >> 2) * 64, wn = (wid & 3) * 64;
    #pragma unroll
    for (int mt = 0; mt < 4; mt++) {
        #pragma unroll
        for (int nt = 0; nt < 8; nt++) {
            int col = ncol0 + wn + nt * 8 + 2 * tig;
            #pragma unroll
            for (int half = 0; half < 2; half++) {
                int row = m0 + wm + mt * 16 + gid + half * 8;
                size_t idx = (size_t)row * D_ + col;
                float2 cc = *(const float2*)(ctx + idx);
                float2 o;
                o.x = cc.x + siluf_(acc[mt][nt][half*2+0] + bc[col]);
                o.y = cc.y + siluf_(acc[mt][nt][half*2+1] + bc[col+1]);
                *(float2*)(out_ctx + idx) = o;
            }
        }
    }
}

// ---------------------------------------------------------------------------
// Chunked scan, float4 lanes. h_t = a_t*h_{t-1} + x_t*sqrt(clip(1-a^2))
// grid (2, NCHUNK, B_), 128 threads. NCHUNK=128 (measured best).
// ---------------------------------------------------------------------------
__global__ void scan1_kernel() {
    int d4 = blockIdx.x * 128 + threadIdx.x;
    int c = blockIdx.y, b = blockIdx.z;
    size_t base = ((size_t)b * L_ + (size_t)c * CLEN) * 256 + d4;
    const float4* a4 = (const float4*)g_alpha;
    const float4* x4 = (const float4*)g_x;
    float4* h4 = (float4*)g_h;
    float4 h = make_float4(0.f, 0.f, 0.f, 0.f);
    float4 A = make_float4(1.f, 1.f, 1.f, 1.f);
    #pragma unroll 4
    for (int t = 0; t < CLEN; t++) {
        size_t idx = base + (size_t)t * 256;
        float4 a = a4[idx];
        float4 x = x4[idx];
        float4 ws;
        ws.x = sqrtf(fmaxf(1.f - a.x * a.x, 1e-6f));
        ws.y = sqrtf(fmaxf(1.f - a.y * a.y, 1e-6f));
        ws.z = sqrtf(fmaxf(1.f - a.z * a.z, 1e-6f));
        ws.w = sqrtf(fmaxf(1.f - a.w * a.w, 1e-6f));
        h.x = fmaf(a.x, h.x, x.x * ws.x);
        h.y = fmaf(a.y, h.y, x.y * ws.y);
        h.z = fmaf(a.z, h.z, x.z * ws.z);
        h.w = fmaf(a.w, h.w, x.w * ws.w);
        A.x *= a.x; A.y *= a.y; A.z *= a.z; A.w *= a.w;
        h4[idx] = h;
    }
    int sidx = (b * NCHUNK + c) * 256 + d4;
    ((float4*)g_hend)[sidx] = h;
    ((float4*)g_Aprod)[sidx] = A;
}

// carry chain across chunks. grid (8, B_), 128 threads
__global__ __launch_bounds__(128) void scan2_kernel() {
    int d = blockIdx.x * 128 + threadIdx.x;
    int b = blockIdx.y;
    float carry = 0.f;
    // batches of 16 to bound register pressure while keeping MLP high
    #pragma unroll
    for (int cb = 0; cb < NCHUNK; cb += 16) {
        float Ap[16], He[16];
        #pragma unroll
        for (int i = 0; i < 16; i++) {
            int sidx = (b * NCHUNK + cb + i) * D_ + d;
            Ap[i] = g_Aprod[sidx];
            He[i] = g_hend[sidx];
        }
        #pragma unroll
        for (int i = 0; i < 16; i++) {
            g_carry[(b * NCHUNK + cb + i) * D_ + d] = carry;
            carry = fmaf(Ap[i], carry, He[i]);
        }
    }
}

// Pass 3: h += A*carry; o_out = out + h; g_h16 = half(h). No g_h rewrite.
__global__ void scan3_out_kernel(const float* __restrict__ out_in,
                                 float* __restrict__ o_out) {
    int d4 = blockIdx.x * 128 + threadIdx.x;
    int c = blockIdx.y, b = blockIdx.z;
    size_t base = ((size_t)b * L_ + (size_t)c * CLEN) * 256 + d4;
    const float4* a4 = (const float4*)g_alpha;
    const float4* h4 = (const float4*)g_h;
    const float4* o4 = (const float4*)out_in;
    float4* oo4 = (float4*)o_out;
    uint2* h16 = (uint2*)g_h16;

    if (c == 0) {
        #pragma unroll 4
        for (int t = 0; t < CLEN; t++) {
            size_t idx = base + (size_t)t * 256;
            float4 h = h4[idx];
            float4 o = o4[idx];
            o.x += h.x; o.y += h.y; o.z += h.z; o.w += h.w;
            oo4[idx] = o;
            __half2 lo = __floats2half2_rn(h.x, h.y);
            __half2 hi = __floats2half2_rn(h.z, h.w);
            h16[idx] = make_uint2(*(uint32_t*)&lo, *(uint32_t*)&hi);
        }
        return;
    }
    float4 carry = ((const float4*)g_carry)[(b * NCHUNK + c) * 256 + d4];
    float4 A = make_float4(1.f, 1.f, 1.f, 1.f);
    #pragma unroll 4
    for (int t = 0; t < CLEN; t++) {
        size_t idx = base + (size_t)t * 256;
        float4 a = a4[idx];
        A.x *= a.x; A.y *= a.y; A.z *= a.z; A.w *= a.w;
        float4 h = h4[idx];
        h.x = fmaf(A.x, carry.x, h.x);
        h.y = fmaf(A.y, carry.y, h.y);
        h.z = fmaf(A.z, carry.z, h.z);
        h.w = fmaf(A.w, carry.w, h.w);
        float4 o = o4[idx];
        o.x += h.x; o.y += h.y; o.z += h.z; o.w += h.w;
        oo4[idx] = o;
        __half2 lo = __floats2half2_rn(h.x, h.y);
        __half2 hi = __floats2half2_rn(h.z, h.w);
        h16[idx] = make_uint2(*(uint32_t*)&lo, *(uint32_t*)&hi);
    }
}

// ---------------------------------------------------------------------------
extern "C" void kernel_launch(void* const* d_in, const int* in_sizes, int n_in,
                              void* d_out, int out_size)
{
    const float* v    = (const float*)d_in[0];
    const float* ctx  = (const float*)d_in[1];
    const float* out  = (const float*)d_in[2];
    const float* alog = (const float*)d_in[3];
    const float* g    = (const float*)d_in[4];
    const float* Wa   = (const float*)d_in[5];
    const float* ba   = (const float*)d_in[6];
    const float* Wb   = (const float*)d_in[7];
    const float* bb   = (const float*)d_in[8];
    const float* Wc   = (const float*)d_in[9];
    const float* bc   = (const float*)d_in[10];

    float* o      = (float*)d_out;
    float* o_v    = o;
    float* o_ctx  = o + (size_t)TOT;
    float* o_out  = o + (size_t)2 * TOT;
    float* o_alog = o + (size_t)3 * TOT;

    static int smem_set = 0;
    if (!smem_set) {
        cudaFuncSetAttribute(gemm_ab_kernel,  cudaFuncAttributeMaxDynamicSharedMemorySize, SMEM_BYTES);
        cudaFuncSetAttribute(gemm_ctx_kernel, cudaFuncAttributeMaxDynamicSharedMemorySize, SMEM_BYTES);
        smem_set = 1;
    }

    cudaMemcpyAsync(o_alog, alog, (size_t)TOT * sizeof(float), cudaMemcpyDeviceToDevice, 0);

    transpose3_kernel<<<dim3(32, 32, 3), dim3(32, 8)>>>(Wa, Wb, Wc);
    rms_kernel<<<M_, 256>>>(ctx, g);
    gemm_ab_kernel<<<dim3(8, 128), 256, SMEM_BYTES>>>(ba, bb, v, o_v);
    scan1_kernel<<<dim3(2, NCHUNK, B_), 128>>>();
    scan2_kernel<<<dim3(8, B_), 128>>>();
    scan3_out_kernel<<<dim3(2, NCHUNK, B_), 128>>>(out, o_out);
    gemm_ctx_kernel<<<dim3(4, 128), 256, SMEM_BYTES>>>(bc, ctx, o_ctx);
}

// round 15
// speedup vs baseline: 1.4543x; 1.4543x over previous
#include <cuda_runtime.h>
#include <cuda_fp16.h>
#include <math.h>
#include <stdint.h>

#define B_ 4
#define L_ 4096
#define D_ 1024
#define M_ (B_*L_)            // 16384 rows
#define TOT (M_*D_)           // 16777216 elements per tensor
#define NCHUNK 128
#define CLEN (L_/NCHUNK)      // 32
#define KT (D_/16)            // 64 k-tiles of 16

// ---- GEMM tiling: block 128(M) x 256(N), 8 warps 2x4, warp tile 64x64, fp16 ----
// EXACT R10 configuration — proven local optimum, do not perturb.
#define STAGES 5
#define AST 24                 // halves per A row (16 + 8 pad) -> 48B, conflict-free
#define BST 24
#define A_STAGE (128*AST)      // 3072 halves
#define B_STAGE (256*BST)      // 6144 halves
#define STAGE_HALVES (A_STAGE + B_STAGE)        // 9216 (18KB)
#define SMEM_BYTES (STAGES*STAGE_HALVES*2)      // 92160

// ---- scratch (device globals: no runtime allocation allowed) ----
__device__ float  g_alpha[TOT];
__device__ __half g_x16  [TOT];     // v * silu(beta_logits), fp16
__device__ __half g_norm16[TOT];
__device__ __half g_h16  [TOT];     // h (provisional after scan1, final after scan3)
__device__ float  g_Aprod[B_*NCHUNK*D_];
__device__ float  g_hend [B_*NCHUNK*D_];
__device__ float  g_carry[B_*NCHUNK*D_];
__device__ __half g_WaT16[D_*D_];
__device__ __half g_WbT16[D_*D_];
__device__ __half g_WcT16[D_*D_];

__device__ __forceinline__ float sigmoidf_(float z) { return 1.f / (1.f + expf(-z)); }
__device__ __forceinline__ float siluf_(float z)    { return z   / (1.f + expf(-z)); }

__device__ __forceinline__ void mma_f16(float c[4],
    uint32_t a0, uint32_t a1, uint32_t a2, uint32_t a3, uint32_t b0, uint32_t b1) {
    asm volatile(
        "mma.sync.aligned.m16n8k16.row.col.f32.f16.f16.f32 "
        "{%0,%1,%2,%3},{%4,%5,%6,%7},{%8,%9},{%0,%1,%2,%3};"
        : "+f"(c[0]), "+f"(c[1]), "+f"(c[2]), "+f"(c[3])
        : "r"(a0), "r"(a1), "r"(a2), "r"(a3), "r"(b0), "r"(b1));
}
__device__ __forceinline__ void cp16(void* dst, const void* src) {
    uint32_t d = (uint32_t)__cvta_generic_to_shared(dst);
    asm volatile("cp.async.cg.shared.global [%0], [%1], 16;" :: "r"(d), "l"(src));
}
#define CP_COMMIT()  asm volatile("cp.async.commit_group;")
#define CP_WAIT3()   asm volatile("cp.async.wait_group 3;")

// ---------------------------------------------------------------------------
// RMS norm -> half output. float4 lanes: 256 threads x 1 float4 = 1024 floats.
// ---------------------------------------------------------------------------
__global__ __launch_bounds__(256) void rms_kernel(
    const float* __restrict__ ctx, const float* __restrict__ g)
{
    int row = blockIdx.x;
    float4 xv = ((const float4*)(ctx + (size_t)row * D_))[threadIdx.x];
    float s = xv.x * xv.x + xv.y * xv.y + xv.z * xv.z + xv.w * xv.w;
    __shared__ float red[8];
    #pragma unroll
    for (int o = 16; o > 0; o >>= 1) s += __shfl_xor_sync(0xffffffffu, s, o);
    if ((threadIdx.x & 31) == 0) red[threadIdx.x >> 5] = s;
    __syncthreads();
    if (threadIdx.x < 8) {
        float t = red[threadIdx.x];
        #pragma unroll
        for (int o = 4; o > 0; o >>= 1) t += __shfl_xor_sync(0xffu, t, o);
        if (threadIdx.x == 0) red[0] = t;
    }
    __syncthreads();
    float inv = rsqrtf(red[0] * (1.f / D_) + 1e-6f);
    float4 gv = ((const float4*)g)[threadIdx.x];
    __half2 lo = __floats2half2_rn(xv.x * inv * gv.x, xv.y * inv * gv.y);
    __half2 hi = __floats2half2_rn(xv.z * inv * gv.z, xv.w * inv * gv.w);
    ((uint2*)(g_norm16 + (size_t)row * D_))[threadIdx.x] =
        make_uint2(*(uint32_t*)&lo, *(uint32_t*)&hi);
}

// ---------------------------------------------------------------------------
// Transpose + fp32->fp16 convert of weights: WT16[n*D+k] = half(W[k*D+n])
// ---------------------------------------------------------------------------
__global__ void transpose3_kernel(const float* __restrict__ Wa,
                                  const float* __restrict__ Wb,
                                  const float* __restrict__ Wc) {
    __shared__ float t[32][33];
    const float* src = (blockIdx.z == 0) ? Wa : (blockIdx.z == 1) ? Wb : Wc;
    __half* dst = (blockIdx.z == 0) ? g_WaT16 : (blockIdx.z == 1) ? g_WbT16 : g_WcT16;
    int x = blockIdx.x * 32 + threadIdx.x;
    int y0 = blockIdx.y * 32;
    #pragma unroll
    for (int j = 0; j < 32; j += 8)
        t[threadIdx.y + j][threadIdx.x] = src[(size_t)(y0 + threadIdx.y + j) * D_ + x];
    __syncthreads();
    int x2 = blockIdx.y * 32 + threadIdx.x;
    int y2 = blockIdx.x * 32;
    #pragma unroll
    for (int j = 0; j < 32; j += 8)
        dst[(size_t)(y2 + threadIdx.y + j) * D_ + x2] = __float2half(t[threadIdx.x][threadIdx.y + j]);
}

// ---------------------------------------------------------------------------
// fp16 mainloop — EXACT R7/R10 structure (5 stages, WAIT3, two barriers,
// loads after compute, 256 threads). Measured-good; do not perturb.
// ---------------------------------------------------------------------------
__device__ __forceinline__ void gemm_core(
    __half* sm, const __half* __restrict__ A16, const __half* __restrict__ WT,
    int m0, int ncol0, float acc[4][8][4])
{
    const int tid = threadIdx.x;

    auto ld_stage = [&](int stage, int kt) {
        const int k0 = kt * 16;
        __half* As = sm + stage * STAGE_HALVES;
        __half* Bs = As + A_STAGE;
        {   // A: 128 rows x 2 chunks of 8 halves
            int r = tid >> 1, q = tid & 1;
            cp16(As + r * AST + q * 8, A16 + (size_t)(m0 + r) * D_ + k0 + q * 8);
        }
        #pragma unroll
        for (int i = 0; i < 2; i++) {   // B: 256 rows x 2 chunks
            int idx = tid + i * 256;
            int r = idx >> 1, q = idx & 1;
            cp16(Bs + r * BST + q * 8, WT + (size_t)(ncol0 + r) * D_ + k0 + q * 8);
        }
    };

    const int lane = tid & 31;
    const int gid = lane >> 2, tig = lane & 3;
    const int wid = tid >> 5;
    const int wm = (wid >> 2) * 64;       // 0 / 64
    const int wn = (wid & 3) * 64;        // 0..192

    #pragma unroll
    for (int s = 0; s < STAGES - 1; s++) { ld_stage(s, s); CP_COMMIT(); }

    int s_cur = 0, s_ld = STAGES - 1;
    for (int kt = 0; kt < KT; kt++) {
        CP_WAIT3();
        __syncthreads();

        const __half* as = sm + s_cur * STAGE_HALVES;
        const __half* bs = as + A_STAGE;

        uint32_t af[4][4], bf[8][2];
        #pragma unroll
        for (int mt = 0; mt < 4; mt++) {
            int r = wm + mt * 16 + gid;
            af[mt][0] = *(const uint32_t*)(as + r * AST + 2 * tig);
            af[mt][1] = *(const uint32_t*)(as + (r + 8) * AST + 2 * tig);
            af[mt][2] = *(const uint32_t*)(as + r * AST + 2 * tig + 8);
            af[mt][3] = *(const uint32_t*)(as + (r + 8) * AST + 2 * tig + 8);
        }
        #pragma unroll
        for (int nt = 0; nt < 8; nt++) {
            int col = wn + nt * 8 + gid;
            bf[nt][0] = *(const uint32_t*)(bs + col * BST + 2 * tig);
            bf[nt][1] = *(const uint32_t*)(bs + col * BST + 2 * tig + 8);
        }
        #pragma unroll
        for (int mt = 0; mt < 4; mt++)
            #pragma unroll
            for (int nt = 0; nt < 8; nt++)
                mma_f16(acc[mt][nt], af[mt][0], af[mt][1], af[mt][2], af[mt][3],
                        bf[nt][0], bf[nt][1]);

        __syncthreads();     // all warps done with s_ld's buffer before overwrite

        int nk = kt + STAGES - 1;
        if (nk < KT) ld_stage(s_ld, nk);
        CP_COMMIT();
        if (++s_cur == STAGES) s_cur = 0;
        if (++s_ld == STAGES) s_ld = 0;
    }
}

// ---------------------------------------------------------------------------
// GEMM 1+2: alpha = sigmoid(.@Wa+ba) -> g_alpha (fp32);
//           beta path: g_x16 = half(v*silu(.@Wb+bb)), o_v = v. grid (8,128)
// ---------------------------------------------------------------------------
__global__ __launch_bounds__(256, 1) void gemm_ab_kernel(
    const float* __restrict__ ba, const float* __restrict__ bb,
    const float* __restrict__ v, float* __restrict__ o_v)
{
    extern __shared__ __half sm[];
    const int m0 = blockIdx.y * 128;
    const bool isA = (blockIdx.x < 4);
    const int ncol0 = (isA ? blockIdx.x : blockIdx.x - 4) * 256;
    const __half* WT  = isA ? g_WaT16 : g_WbT16;
    const float* bias = isA ? ba : bb;

    float acc[4][8][4];
    #pragma unroll
    for (int i = 0; i < 4; i++)
        #pragma unroll
        for (int j = 0; j < 8; j++)
            #pragma unroll
            for (int k = 0; k < 4; k++) acc[i][j][k] = 0.f;

    gemm_core(sm, g_norm16, WT, m0, ncol0, acc);

    const int lane = threadIdx.x & 31;
    const int gid = lane >> 2, tig = lane & 3;
    const int wid = threadIdx.x >> 5;
    const int wm = (wid >> 2) * 64, wn = (wid & 3) * 64;
    #pragma unroll
    for (int mt = 0; mt < 4; mt++) {
        #pragma unroll
        for (int nt = 0; nt < 8; nt++) {
            int col = ncol0 + wn + nt * 8 + 2 * tig;
            #pragma unroll
            for (int half = 0; half < 2; half++) {
                int row = m0 + wm + mt * 16 + gid + half * 8;
                size_t idx = (size_t)row * D_ + col;
                float z0 = acc[mt][nt][half*2+0] + bias[col];
                float z1 = acc[mt][nt][half*2+1] + bias[col+1];
                if (isA) {
                    float2 o; o.x = sigmoidf_(z0); o.y = sigmoidf_(z1);
                    *(float2*)(g_alpha + idx) = o;
                } else {
                    float2 vv = *(const float2*)(v + idx);
                    __half2 xp = __floats2half2_rn(vv.x * siluf_(z0), vv.y * siluf_(z1));
                    *(uint32_t*)(g_x16 + idx) = *(uint32_t*)&xp;
                    *(float2*)(o_v + idx) = vv;
                }
            }
        }
    }
}

// ---------------------------------------------------------------------------
// GEMM 3: ctx_out = ctx + silu(h @ Wc + bc). grid (4, 128)
// ---------------------------------------------------------------------------
__global__ __launch_bounds__(256, 1) void gemm_ctx_kernel(
    const float* __restrict__ bc,
    const float* __restrict__ ctx, float* __restrict__ out_ctx)
{
    extern __shared__ __half sm[];
    const int m0 = blockIdx.y * 128;
    const int ncol0 = blockIdx.x * 256;

    float acc[4][8][4];
    #pragma unroll
    for (int i = 0; i < 4; i++)
        #pragma unroll
        for (int j = 0; j < 8; j++)
            #pragma unroll
            for (int k = 0; k < 4; k++) acc[i][j][k] = 0.f;

    gemm_core(sm, g_h16, g_WcT16, m0, ncol0, acc);

    const int lane = threadIdx.x & 31;
    const int gid = lane >> 2, tig = lane & 3;
    const int wid = threadIdx.x >> 5;
    const int wm = (wid >> 2) * 64, wn = (wid & 3) * 64;
    #pragma unroll
    for (int mt = 0; mt < 4; mt++) {
        #pragma unroll
        for (int nt = 0; nt < 8; nt++) {
            int col = ncol0 + wn + nt * 8 + 2 * tig;
            #pragma unroll
            for (int half = 0; half < 2; half++) {
                int row = m0 + wm + mt * 16 + gid + half * 8;
                size_t idx = (size_t)row * D_ + col;
                float2 cc = *(const float2*)(ctx + idx);
                float2 o;
                o.x = cc.x + siluf_(acc[mt][nt][half*2+0] + bc[col]);
                o.y = cc.y + siluf_(acc[mt][nt][half*2+1] + bc[col+1]);
                *(float2*)(out_ctx + idx) = o;
            }
        }
    }
}

// ---------------------------------------------------------------------------
// Chunked scan. h_t = a_t*h_{t-1} + x_t*sqrt(clip(1-a^2)); x from fp16,
// provisional h stored fp16. grid (2, NCHUNK, B_), 128 threads.
// ---------------------------------------------------------------------------
__global__ void scan1_kernel() {
    int d4 = blockIdx.x * 128 + threadIdx.x;
    int c = blockIdx.y, b = blockIdx.z;
    size_t base = ((size_t)b * L_ + (size_t)c * CLEN) * 256 + d4;
    const float4* a4 = (const float4*)g_alpha;
    const uint2* x16 = (const uint2*)g_x16;
    uint2* h16 = (uint2*)g_h16;
    float4 h = make_float4(0.f, 0.f, 0.f, 0.f);
    float4 A = make_float4(1.f, 1.f, 1.f, 1.f);
    #pragma unroll 4
    for (int t = 0; t < CLEN; t++) {
        size_t idx = base + (size_t)t * 256;
        float4 a = a4[idx];
        uint2 xp = x16[idx];
        float2 xl = __half22float2(*(__half2*)&xp.x);
        float2 xh = __half22float2(*(__half2*)&xp.y);
        float4 ws;
        ws.x = sqrtf(fmaxf(1.f - a.x * a.x, 1e-6f));
        ws.y = sqrtf(fmaxf(1.f - a.y * a.y, 1e-6f));
        ws.z = sqrtf(fmaxf(1.f - a.z * a.z, 1e-6f));
        ws.w = sqrtf(fmaxf(1.f - a.w * a.w, 1e-6f));
        h.x = fmaf(a.x, h.x, xl.x * ws.x);
        h.y = fmaf(a.y, h.y, xl.y * ws.y);
        h.z = fmaf(a.z, h.z, xh.x * ws.z);
        h.w = fmaf(a.w, h.w, xh.y * ws.w);
        A.x *= a.x; A.y *= a.y; A.z *= a.z; A.w *= a.w;
        __half2 lo = __floats2half2_rn(h.x, h.y);
        __half2 hi = __floats2half2_rn(h.z, h.w);
        h16[idx] = make_uint2(*(uint32_t*)&lo, *(uint32_t*)&hi);
    }
    int sidx = (b * NCHUNK + c) * 256 + d4;
    ((float4*)g_hend)[sidx] = h;      // fp32 chunk-end state: carry chain stays exact
    ((float4*)g_Aprod)[sidx] = A;
}

// carry chain across chunks. grid (8, B_), 128 threads
__global__ __launch_bounds__(128) void scan2_kernel() {
    int d = blockIdx.x * 128 + threadIdx.x;
    int b = blockIdx.y;
    float carry = 0.f;
    #pragma unroll
    for (int cb = 0; cb < NCHUNK; cb += 16) {
        float Ap[16], He[16];
        #pragma unroll
        for (int i = 0; i < 16; i++) {
            int sidx = (b * NCHUNK + cb + i) * D_ + d;
            Ap[i] = g_Aprod[sidx];
            He[i] = g_hend[sidx];
        }
        #pragma unroll
        for (int i = 0; i < 16; i++) {
            g_carry[(b * NCHUNK + cb + i) * D_ + d] = carry;
            carry = fmaf(Ap[i], carry, He[i]);
        }
    }
}

// Pass 3: h = h16 + A*carry; o_out = out + h; g_h16 = half(h).
__global__ void scan3_out_kernel(const float* __restrict__ out_in,
                                 float* __restrict__ o_out) {
    int d4 = blockIdx.x * 128 + threadIdx.x;
    int c = blockIdx.y, b = blockIdx.z;
    size_t base = ((size_t)b * L_ + (size_t)c * CLEN) * 256 + d4;
    const float4* a4 = (const float4*)g_alpha;
    const float4* o4 = (const float4*)out_in;
    float4* oo4 = (float4*)o_out;
    uint2* h16 = (uint2*)g_h16;

    if (c == 0) {   // no carry: h16 already final; just produce o_out
        #pragma unroll 4
        for (int t = 0; t < CLEN; t++) {
            size_t idx = base + (size_t)t * 256;
            uint2 hp = h16[idx];
            float2 hl = __half22float2(*(__half2*)&hp.x);
            float2 hh = __half22float2(*(__half2*)&hp.y);
            float4 o = o4[idx];
            o.x += hl.x; o.y += hl.y; o.z += hh.x; o.w += hh.y;
            oo4[idx] = o;
        }
        return;
    }
    float4 carry = ((const float4*)g_carry)[(b * NCHUNK + c) * 256 + d4];
    float4 A = make_float4(1.f, 1.f, 1.f, 1.f);
    #pragma unroll 4
    for (int t = 0; t < CLEN; t++) {
        size_t idx = base + (size_t)t * 256;
        float4 a = a4[idx];
        A.x *= a.x; A.y *= a.y; A.z *= a.z; A.w *= a.w;
        uint2 hp = h16[idx];
        float2 hl = __half22float2(*(__half2*)&hp.x);
        float2 hh = __half22float2(*(__half2*)&hp.y);
        float4 h;
        h.x = fmaf(A.x, carry.x, hl.x);
        h.y = fmaf(A.y, carry.y, hl.y);
        h.z = fmaf(A.z, carry.z, hh.x);
        h.w = fmaf(A.w, carry.w, hh.y);
        float4 o = o4[idx];
        o.x += h.x; o.y += h.y; o.z += h.z; o.w += h.w;
        oo4[idx] = o;
        __half2 lo = __floats2half2_rn(h.x, h.y);
        __half2 hi = __floats2half2_rn(h.z, h.w);
        h16[idx] = make_uint2(*(uint32_t*)&lo, *(uint32_t*)&hi);
    }
}

// ---------------------------------------------------------------------------
extern "C" void kernel_launch(void* const* d_in, const int* in_sizes, int n_in,
                              void* d_out, int out_size)
{
    const float* v    = (const float*)d_in[0];
    const float* ctx  = (const float*)d_in[1];
    const float* out  = (const float*)d_in[2];
    const float* alog = (const float*)d_in[3];
    const float* g    = (const float*)d_in[4];
    const float* Wa   = (const float*)d_in[5];
    const float* ba   = (const float*)d_in[6];
    const float* Wb   = (const float*)d_in[7];
    const float* bb   = (const float*)d_in[8];
    const float* Wc   = (const float*)d_in[9];
    const float* bc   = (const float*)d_in[10];

    float* o      = (float*)d_out;
    float* o_v    = o;
    float* o_ctx  = o + (size_t)TOT;
    float* o_out  = o + (size_t)2 * TOT;
    float* o_alog = o + (size_t)3 * TOT;

    static int smem_set = 0;
    if (!smem_set) {
        cudaFuncSetAttribute(gemm_ab_kernel,  cudaFuncAttributeMaxDynamicSharedMemorySize, SMEM_BYTES);
        cudaFuncSetAttribute(gemm_ctx_kernel, cudaFuncAttributeMaxDynamicSharedMemorySize, SMEM_BYTES);
        smem_set = 1;
    }

    cudaMemcpyAsync(o_alog, alog, (size_t)TOT * sizeof(float), cudaMemcpyDeviceToDevice, 0);

    transpose3_kernel<<<dim3(32, 32, 3), dim3(32, 8)>>>(Wa, Wb, Wc);
    rms_kernel<<<M_, 256>>>(ctx, g);
    gemm_ab_kernel<<<dim3(8, 128), 256, SMEM_BYTES>>>(ba, bb, v, o_v);
    scan1_kernel<<<dim3(2, NCHUNK, B_), 128>>>();
    scan2_kernel<<<dim3(8, B_), 128>>>();
    scan3_out_kernel<<<dim3(2, NCHUNK, B_), 128>>>(out, o_out);
    gemm_ctx_kernel<<<dim3(4, 128), 256, SMEM_BYTES>>>(bc, ctx, o_ctx);
}